// round 16
// baseline (speedup 1.0000x reference)
#include <cuda_runtime.h>
#include <cuda_bf16.h>
#include <math.h>
#include <stdint.h>

#define NOBJ 50000
#define NTRI 100000
#define DIN_ 128
#define H_   512
#define DOUT_ 128

// ---------------- scratch (device globals: no allocs allowed) ----------------
static __device__ float    g_cand[(size_t)2 * NTRI * H_];   // fp32 (pool)
static __device__ float    g_z[NOBJ];
static __device__ float    g_bu[H_];
static __device__ float    g_c0[1];
static __device__ int      g_cnt[NOBJ];
static __device__ int      g_off[NOBJ + 1];
static __device__ int      g_cur[NOBJ];
static __device__ int      g_eidx[2 * NTRI];

// 2-term bf16 split planes [2][M][K]
static __device__ __nv_bfloat16 g_objs [(size_t)2 * NOBJ * DIN_];
static __device__ __nv_bfloat16 g_preds[(size_t)2 * NTRI * DIN_];
static __device__ __nv_bfloat16 g_h1s  [(size_t)2 * NTRI * H_];
static __device__ __nv_bfloat16 g_prevs[(size_t)2 * NOBJ * H_];
static __device__ __nv_bfloat16 g_us   [(size_t)2 * NOBJ * H_];
static __device__ __nv_bfloat16 g_h2s  [(size_t)2 * NOBJ * H_];
static __device__ __nv_bfloat16 g_pooleds[(size_t)2 * NOBJ * H_];
static __device__ __nv_bfloat16 g_simws[2 * 512 * 512];
static __device__ __nv_bfloat16 g_Ss   [2 * 512 * 512];

// 2-term bf16 split weights, [2][N][K]
static __device__ __nv_bfloat16 g_wproj[2 * 512 * 128];
static __device__ __nv_bfloat16 g_wn1a[2 * 512 * 384];
static __device__ __nv_bfloat16 g_wn1b[2 * 1152 * 512];
static __device__ __nv_bfloat16 g_wn2a[2 * 512 * 512];
static __device__ __nv_bfloat16 g_wn2b[2 * 128 * 512];

// ---------------- fork/join stream resources (host objects, created at load) ----------------
struct StreamRes {
    cudaStream_t s2;
    cudaEvent_t evFork, evInp, evW2, evJoin;
    StreamRes() {
        cudaStreamCreateWithFlags(&s2, cudaStreamNonBlocking);
        cudaEventCreateWithFlags(&evFork, cudaEventDisableTiming);
        cudaEventCreateWithFlags(&evInp,  cudaEventDisableTiming);
        cudaEventCreateWithFlags(&evW2,   cudaEventDisableTiming);
        cudaEventCreateWithFlags(&evJoin, cudaEventDisableTiming);
    }
};
static StreamRes g_sr;

// ---------------- helpers ----------------
__device__ __forceinline__ void split2(float x, unsigned short& hi, unsigned short& lo) {
    __nv_bfloat16 h = __float2bfloat16_rn(x);
    __nv_bfloat16 l = __float2bfloat16_rn(x - __bfloat162float(h));
    hi = __bfloat16_as_ushort(h);
    lo = __bfloat16_as_ushort(l);
}
__device__ __forceinline__ float2 bf2(uint32_t u) {
    return make_float2(__bfloat162float(__ushort_as_bfloat16((unsigned short)(u & 0xffff))),
                       __bfloat162float(__ushort_as_bfloat16((unsigned short)(u >> 16))));
}
__device__ __forceinline__ uint32_t smem_u32(const void* p) {
    uint32_t a;
    asm("{ .reg .u64 t; cvta.to.shared.u64 t, %1; cvt.u32.u64 %0, t; }" : "=r"(a) : "l"(p));
    return a;
}
__device__ __forceinline__ void cpa16(uint32_t dst, const void* src, uint32_t sz) {
    asm volatile("cp.async.cg.shared.global [%0], [%1], 16, %2;"
                 :: "r"(dst), "l"(src), "r"(sz) : "memory");
}
#define CPA_COMMIT() asm volatile("cp.async.commit_group;" ::: "memory")
#define CPA_WAIT0()  asm volatile("cp.async.wait_group 0;" ::: "memory")

__device__ __forceinline__ void mma16816(float* d, const uint32_t* a, uint32_t b0, uint32_t b1) {
    asm volatile(
        "mma.sync.aligned.m16n8k16.row.col.f32.bf16.bf16.f32 "
        "{%0,%1,%2,%3}, {%4,%5,%6,%7}, {%8,%9}, {%0,%1,%2,%3};"
        : "+f"(d[0]), "+f"(d[1]), "+f"(d[2]), "+f"(d[3])
        : "r"(a[0]), "r"(a[1]), "r"(a[2]), "r"(a[3]), "r"(b0), "r"(b1));
}
__device__ __forceinline__ void ldsm4(uint32_t* r, uint32_t addr) {
    asm volatile("ldmatrix.sync.aligned.m8n8.x4.shared.b16 {%0,%1,%2,%3}, [%4];"
                 : "=r"(r[0]), "=r"(r[1]), "=r"(r[2]), "=r"(r[3]) : "r"(addr));
}

// ---------------- prologue split kernels ----------------
__global__ void wsplitA(const float* __restrict__ n1w1, __nv_bfloat16* __restrict__ wn1a)
{
    const int idx = blockIdx.x * 256 + threadIdx.x;
    const size_t NK = (size_t)512 * 384;
    if (idx >= (int)NK) return;
    const int n = idx / 384, k = idx - n * 384;
    unsigned short a, bb;
    split2(n1w1[(size_t)k * 512 + n], a, bb);
    wn1a[idx]      = __ushort_as_bfloat16(a);
    wn1a[NK + idx] = __ushort_as_bfloat16(bb);
}

// [0,2304) wn1b | [2304,2560) wproj | [2560,3584) wn2a | [3584,3840) wn2b | [3840,4864) simws
__global__ void wsplitR(const float* __restrict__ n1w2, const float* __restrict__ projw,
                        const float* __restrict__ n2w1, const float* __restrict__ n2w2,
                        const float* __restrict__ simw,
                        __nv_bfloat16* __restrict__ wn1b, __nv_bfloat16* __restrict__ wproj,
                        __nv_bfloat16* __restrict__ wn2a, __nv_bfloat16* __restrict__ wn2b,
                        __nv_bfloat16* __restrict__ simws)
{
    const int b = blockIdx.x;
    const float* W; __nv_bfloat16* out; int Kd, Nd, base; bool trans = true;
    if (b < 2304)      { W = n1w2;  out = wn1b;  Kd = 512; Nd = 1152; base = 0; }
    else if (b < 2560) { W = projw; out = wproj; Kd = 128; Nd = 512;  base = 2304; }
    else if (b < 3584) { W = n2w1;  out = wn2a;  Kd = 512; Nd = 512;  base = 2560; }
    else if (b < 3840) { W = n2w2;  out = wn2b;  Kd = 512; Nd = 128;  base = 3584; }
    else               { W = simw;  out = simws; Kd = 512; Nd = 512;  base = 3840; trans = false; }
    const int idx = (b - base) * 256 + threadIdx.x;
    const size_t NK = (size_t)Nd * Kd;
    if (idx >= (int)NK) return;
    float v;
    if (trans) { const int n = idx / Kd, k = idx - n * Kd; v = W[(size_t)k * Nd + n]; }
    else       v = W[idx];
    unsigned short a, bb;
    split2(v, a, bb);
    out[idx]      = __ushort_as_bfloat16(a);
    out[NK + idx] = __ushort_as_bfloat16(bb);
}

// vectorized input split: one thread = 4 consecutive floats
__global__ void isplit2v(const float4* __restrict__ obj, const float4* __restrict__ pred,
                         __nv_bfloat16* __restrict__ objs, __nv_bfloat16* __restrict__ preds)
{
    const int b = blockIdx.x;
    const float4* src; __nv_bfloat16* dst; int n4, idx;
    if (b < 6250) { src = obj;  dst = objs;  n4 = NOBJ * DIN_ / 4; idx = b * 256 + threadIdx.x; }
    else          { src = pred; dst = preds; n4 = NTRI * DIN_ / 4; idx = (b - 6250) * 256 + threadIdx.x; }
    if (idx >= n4) return;
    const float4 v = src[idx];
    unsigned short h0, l0, h1, l1, h2, l2, h3, l3;
    split2(v.x, h0, l0); split2(v.y, h1, l1);
    split2(v.z, h2, l2); split2(v.w, h3, l3);
    *(uint2*)(dst + idx * 4) =
        make_uint2((uint32_t)h0 | ((uint32_t)h1 << 16), (uint32_t)h2 | ((uint32_t)h3 << 16));
    *(uint2*)(dst + (size_t)n4 * 4 + idx * 4) =
        make_uint2((uint32_t)l0 | ((uint32_t)l1 << 16), (uint32_t)l2 | ((uint32_t)l3 << 16));
}

__global__ void buk(const float* __restrict__ simw, const float* __restrict__ simb,
                    float* __restrict__ bu, float* __restrict__ c0)
{
    const int warp = (blockIdx.x * blockDim.x + threadIdx.x) >> 5;
    const int lane = threadIdx.x & 31;
    if (warp > H_) return;
    const float4* a = (warp < H_) ? (const float4*)(simw + (size_t)warp * H_)
                                  : (const float4*)simb;
    const float4* b = (const float4*)simb;
    float s = 0.f;
    #pragma unroll
    for (int q = 0; q < 4; q++) {
        float4 x = a[lane + q * 32], y = b[lane + q * 32];
        s += x.x * y.x + x.y * y.y + x.z * y.z + x.w * y.w;
    }
    #pragma unroll
    for (int o = 16; o; o >>= 1) s += __shfl_down_sync(0xffffffffu, s, o);
    if (lane == 0) {
        if (warp < H_) bu[warp] = s;
        else           c0[0] = s;
    }
}

// ---------------- HMMA GEMM: D[M,N] = A[M,K] @ Ws^T ----------------
// CTA tile 64x128, 8 warps (2x4), warp tile 32x32, BK=32, 3 CTAs/SM.
#define APITCH 80
#define APL    (64 * APITCH)                  // 5120 B per A plane
#define BPL    (128 * APITCH)                 // 10240 B per B plane
#define BUFSZ  (2 * APL + 2 * BPL)            // 30720 B
#define SMEMB  (2 * BUFSZ)                    // 61440 B

template<int AMODE, int OMODE, bool RELU, bool HASBIAS>
__global__ __launch_bounds__(256, 3)
void mmak(const __nv_bfloat16* __restrict__ As,
          const __nv_bfloat16* __restrict__ Wt,
          const float* __restrict__ bias, float* __restrict__ Cf,
          __nv_bfloat16* __restrict__ Cs,
          int M, int N, int K,
          const __nv_bfloat16* __restrict__ objs, const __nv_bfloat16* __restrict__ preds,
          const int* __restrict__ edges,
          float* __restrict__ outp, float* __restrict__ candp)
{
    extern __shared__ __align__(16) unsigned char sm[];
    const int tid = threadIdx.x;
    const int lane = tid & 31, wid = tid >> 5;
    const int wr = wid >> 2, wc = wid & 3;           // 2 x 4 warps
    const int bm = blockIdx.y * 64, bn = blockIdx.x * 128;
    const size_t MK = (size_t)M * K, NK = (size_t)N * K, MN = (size_t)M * N;
    const uint32_t sb = smem_u32(sm);
    const int arow = lane >> 2, acol = (lane & 3) << 1;
    const int t8 = lane & 7, quad = lane >> 3;

    const uint32_t aoff = (uint32_t)(wr * 32 + t8 + ((quad & 1) << 3)) * APITCH + ((quad >> 1) << 4);
    const uint32_t boff = 2 * APL +
        (uint32_t)(wc * 32 + t8 + ((quad >> 1) << 3)) * APITCH + ((quad & 1) << 4);

    float acc[2][4][4];
    #pragma unroll
    for (int i = 0; i < 2; i++)
        #pragma unroll
        for (int j = 0; j < 4; j++)
            #pragma unroll
            for (int q = 0; q < 4; q++) acc[i][j][q] = 0.f;

    auto stageAsync = [&](int k0, int b) {
        const uint32_t smA = sb + b * BUFSZ;
        const uint32_t smB = smA + 2 * APL;
        // A: 512 16B copies -> 2 per thread
        #pragma unroll
        for (int it = 0; it < 2; it++) {
            const int idx = (it << 8) + tid;
            const int p = idx >> 8, r = (idx >> 2) & 63, seg = idx & 3;
            const int gm = bm + r;
            const int gmc = gm < M ? gm : M - 1;
            const __nv_bfloat16* src;
            if (AMODE == 0) {
                src = As + (size_t)p * MK + (size_t)gmc * K + k0 + seg * 8;
            } else {
                if (k0 < DIN_)
                    src = objs + (size_t)p * ((size_t)NOBJ * DIN_)
                        + (size_t)edges[2 * gmc] * DIN_ + k0 + seg * 8;
                else if (k0 < 2 * DIN_)
                    src = preds + (size_t)p * ((size_t)NTRI * DIN_)
                        + (size_t)gmc * DIN_ + (k0 - DIN_) + seg * 8;
                else
                    src = objs + (size_t)p * ((size_t)NOBJ * DIN_)
                        + (size_t)edges[2 * gmc + 1] * DIN_ + (k0 - 2 * DIN_) + seg * 8;
            }
            cpa16(smA + p * APL + r * APITCH + seg * 16, src, gm < M ? 16u : 0u);
        }
        // B: 1024 16B copies -> 4 per thread
        #pragma unroll
        for (int it = 0; it < 4; it++) {
            const int idx = (it << 8) + tid;
            const int p = idx >> 9, n = (idx >> 2) & 127, seg = idx & 3;
            const __nv_bfloat16* src = Wt + (size_t)p * NK + (size_t)(bn + n) * K + k0 + seg * 8;
            cpa16(smB + p * BPL + n * APITCH + seg * 16, src, 16u);
        }
        CPA_COMMIT();
    };

    auto compute = [&](int b) {
        const uint32_t buf = sb + b * BUFSZ;
        #pragma unroll
        for (int s = 0; s < 2; s++) {
            const uint32_t ksb = s * 32;
            uint32_t afh[2][4], afl[2][4], bh[4][2], bl[4][2];
            #pragma unroll
            for (int i = 0; i < 2; i++)
                ldsm4(afh[i], buf + aoff + i * 16 * APITCH + ksb);
            #pragma unroll
            for (int jj = 0; jj < 2; jj++)
                ldsm4(&bh[jj * 2][0], buf + boff + jj * 16 * APITCH + ksb);
            #pragma unroll
            for (int i = 0; i < 2; i++)
                ldsm4(afl[i], buf + APL + aoff + i * 16 * APITCH + ksb);
            #pragma unroll
            for (int j = 0; j < 4; j++)
                #pragma unroll
                for (int i = 0; i < 2; i++)
                    mma16816(acc[i][j], afh[i], bh[j][0], bh[j][1]);
            #pragma unroll
            for (int jj = 0; jj < 2; jj++)
                ldsm4(&bl[jj * 2][0], buf + BPL + boff + jj * 16 * APITCH + ksb);
            #pragma unroll
            for (int j = 0; j < 4; j++)
                #pragma unroll
                for (int i = 0; i < 2; i++)
                    mma16816(acc[i][j], afl[i], bh[j][0], bh[j][1]);
            #pragma unroll
            for (int j = 0; j < 4; j++)
                #pragma unroll
                for (int i = 0; i < 2; i++)
                    mma16816(acc[i][j], afh[i], bl[j][0], bl[j][1]);
        }
    };

    const int nch = K >> 5;
    stageAsync(0, 0);
    CPA_WAIT0();
    __syncthreads();

    for (int ch = 0; ch < nch; ch++) {
        const int b = ch & 1;
        if (ch + 1 < nch) stageAsync((ch + 1) << 5, b ^ 1);
        compute(b);
        CPA_WAIT0();
        __syncthreads();
    }

    // ---- epilogue ----
    #pragma unroll
    for (int i = 0; i < 2; i++)
        #pragma unroll
        for (int j = 0; j < 4; j++) {
            const int gm0 = bm + wr * 32 + i * 16 + arow;
            const int gn  = bn + wc * 32 + j * 8 + acol;
            float2 bb = make_float2(0.f, 0.f);
            if (HASBIAS) bb = *(const float2*)&bias[gn];
            #pragma unroll
            for (int h = 0; h < 2; h++) {
                const int m = gm0 + h * 8;
                if (m < M) {
                    float x0 = acc[i][j][2 * h]     + bb.x;
                    float x1 = acc[i][j][2 * h + 1] + bb.y;
                    if (RELU) { x0 = fmaxf(x0, 0.f); x1 = fmaxf(x1, 0.f); }
                    if (OMODE == 0) {
                        *(float2*)(Cf + (size_t)m * N + gn) = make_float2(x0, x1);
                    } else if (OMODE == 1) {
                        unsigned short h0, l0, h1, l1;
                        split2(x0, h0, l0); split2(x1, h1, l1);
                        *(uint32_t*)(Cs + (size_t)m * N + gn)      = (uint32_t)h0 | ((uint32_t)h1 << 16);
                        *(uint32_t*)(Cs + MN + (size_t)m * N + gn) = (uint32_t)l0 | ((uint32_t)l1 << 16);
                    } else {
                        float* dst;
                        if (gn < H_)              dst = candp + (size_t)m * H_ + gn;
                        else if (gn < H_ + DOUT_) dst = outp + (size_t)m * DOUT_ + (gn - H_);
                        else                      dst = candp + (size_t)(NTRI + m) * H_ + (gn - H_ - DOUT_);
                        *(float2*)dst = make_float2(x0, x1);
                    }
                }
            }
        }
}

// ---------------- z + CSR build + fused online-softmax pooling ----------------
__global__ void zk3(const __nv_bfloat16* __restrict__ prevs, const float* __restrict__ bu,
                    const float* __restrict__ c0, float* __restrict__ z)
{
    const int row = (blockIdx.x * blockDim.x + threadIdx.x) >> 5;
    const int lane = threadIdx.x & 31;
    if (row >= NOBJ) return;
    const size_t PS = (size_t)NOBJ * H_;
    const uint2* ph = (const uint2*)(prevs + (size_t)row * H_);
    const uint2* pl = (const uint2*)(prevs + PS + (size_t)row * H_);
    float s = 0.f;
    #pragma unroll
    for (int q = 0; q < 4; q++) {
        const int t = lane + q * 32;
        uint2 a = ph[t], b = pl[t];
        float4 w4 = *(const float4*)&bu[t * 4];
        float2 a0 = bf2(a.x), a1 = bf2(a.y), b0 = bf2(b.x), b1 = bf2(b.y);
        s += (a0.x + b0.x) * w4.x + (a0.y + b0.y) * w4.y
           + (a1.x + b1.x) * w4.z + (a1.y + b1.y) * w4.w;
    }
    #pragma unroll
    for (int o = 16; o; o >>= 1) s += __shfl_down_sync(0xffffffffu, s, o);
    if (lane == 0) z[row] = s + c0[0];
}

__global__ void zeroint(int* __restrict__ p, int n)
{
    const int i = blockIdx.x * blockDim.x + threadIdx.x;
    if (i < n) p[i] = 0;
}

__global__ void cntk(const int* __restrict__ edges, int* __restrict__ cnt)
{
    const int e = blockIdx.x * blockDim.x + threadIdx.x;
    if (e >= 2 * NTRI) return;
    const int idx = (e < NTRI) ? edges[2 * e] : edges[2 * (e - NTRI) + 1];
    atomicAdd(cnt + idx, 1);
}

__global__ void scank(const int* __restrict__ cnt, int* __restrict__ off,
                      int* __restrict__ cur)
{
    __shared__ int ssum[1024];
    const int t = threadIdx.x;
    const int CH = (NOBJ + 1023) / 1024;
    const int base = t * CH;
    int s = 0;
    for (int i = 0; i < CH; i++) {
        const int j = base + i;
        if (j < NOBJ) s += cnt[j];
    }
    ssum[t] = s;
    __syncthreads();
    for (int d = 1; d < 1024; d <<= 1) {
        const int v = (t >= d) ? ssum[t - d] : 0;
        __syncthreads();
        ssum[t] += v;
        __syncthreads();
    }
    int run = t ? ssum[t - 1] : 0;
    for (int i = 0; i < CH; i++) {
        const int j = base + i;
        if (j < NOBJ) {
            off[j] = run;
            cur[j] = run;
            run += cnt[j];
        }
    }
    if (t == 1023) off[NOBJ] = ssum[1023];
}

__global__ void fillk(const int* __restrict__ edges, int* __restrict__ cur,
                      int* __restrict__ eidx)
{
    const int e = blockIdx.x * blockDim.x + threadIdx.x;
    if (e >= 2 * NTRI) return;
    const int idx = (e < NTRI) ? edges[2 * e] : edges[2 * (e - NTRI) + 1];
    const int pos = atomicAdd(cur + idx, 1);
    eidx[pos] = e;
}

// warp per object: one pass, online softmax (exact)
__global__ void poolfk(const int* __restrict__ off, const int* __restrict__ eidx,
                       const __nv_bfloat16* __restrict__ us, const float* __restrict__ z,
                       const float* __restrict__ cand, __nv_bfloat16* __restrict__ pooleds)
{
    const int i = (blockIdx.x * blockDim.x + threadIdx.x) >> 5;
    const int lane = threadIdx.x & 31;
    if (i >= NOBJ) return;
    const size_t PS = (size_t)NOBJ * H_;

    float4 uf[4];
    {
        const uint2* uh = (const uint2*)(us + (size_t)i * H_);
        const uint2* ul = (const uint2*)(us + PS + (size_t)i * H_);
        #pragma unroll
        for (int q = 0; q < 4; q++) {
            uint2 h = uh[lane + q * 32], l = ul[lane + q * 32];
            float2 h0 = bf2(h.x), h1 = bf2(h.y), l0 = bf2(l.x), l1 = bf2(l.y);
            uf[q] = make_float4(h0.x + l0.x, h0.y + l0.y, h1.x + l1.x, h1.y + l1.y);
        }
    }
    const float zi = z[i];
    float m = zi, den = 1.f;
    float4 a0 = make_float4(0, 0, 0, 0), a1 = a0, a2 = a0, a3 = a0;

    const int beg = off[i], end = off[i + 1];
    for (int p = beg; p < end; p++) {
        const int e = eidx[p];
        const float4* src = (const float4*)(cand + (size_t)e * H_);
        float4 c0v = src[lane], c1v = src[lane + 32], c2v = src[lane + 64], c3v = src[lane + 96];
        float s = c0v.x * uf[0].x + c0v.y * uf[0].y + c0v.z * uf[0].z + c0v.w * uf[0].w
                + c1v.x * uf[1].x + c1v.y * uf[1].y + c1v.z * uf[1].z + c1v.w * uf[1].w
                + c2v.x * uf[2].x + c2v.y * uf[2].y + c2v.z * uf[2].z + c2v.w * uf[2].w
                + c3v.x * uf[3].x + c3v.y * uf[3].y + c3v.z * uf[3].z + c3v.w * uf[3].w;
        #pragma unroll
        for (int o = 16; o; o >>= 1) s += __shfl_xor_sync(0xffffffffu, s, o);
        const float score = s + zi;
        float w;
        if (score > m) {
            const float sc = expf(m - score);
            den *= sc;
            a0.x *= sc; a0.y *= sc; a0.z *= sc; a0.w *= sc;
            a1.x *= sc; a1.y *= sc; a1.z *= sc; a1.w *= sc;
            a2.x *= sc; a2.y *= sc; a2.z *= sc; a2.w *= sc;
            a3.x *= sc; a3.y *= sc; a3.z *= sc; a3.w *= sc;
            m = score;
            w = 1.f;
        } else {
            w = expf(score - m);
        }
        den += w;
        a0.x += w * c0v.x; a0.y += w * c0v.y; a0.z += w * c0v.z; a0.w += w * c0v.w;
        a1.x += w * c1v.x; a1.y += w * c1v.y; a1.z += w * c1v.z; a1.w += w * c1v.w;
        a2.x += w * c2v.x; a2.y += w * c2v.y; a2.z += w * c2v.z; a2.w += w * c2v.w;
        a3.x += w * c3v.x; a3.y += w * c3v.y; a3.z += w * c3v.z; a3.w += w * c3v.w;
    }

    const float r = 1.0f / den;
    __nv_bfloat16* hi = pooleds + (size_t)i * H_;
    __nv_bfloat16* lo = pooleds + PS + (size_t)i * H_;
    auto st = [&](float4 v, int col) {
        v.x *= r; v.y *= r; v.z *= r; v.w *= r;
        unsigned short h0, l0, h1, l1, h2, l2, h3, l3;
        split2(v.x, h0, l0); split2(v.y, h1, l1);
        split2(v.z, h2, l2); split2(v.w, h3, l3);
        *(uint2*)(hi + col) = make_uint2((uint32_t)h0 | ((uint32_t)h1 << 16),
                                         (uint32_t)h2 | ((uint32_t)h3 << 16));
        *(uint2*)(lo + col) = make_uint2((uint32_t)l0 | ((uint32_t)l1 << 16),
                                         (uint32_t)l2 | ((uint32_t)l3 << 16));
    };
    st(a0, 4 * lane);
    st(a1, 128 + 4 * lane);
    st(a2, 256 + 4 * lane);
    st(a3, 384 + 4 * lane);
}

extern "C" void kernel_launch(void* const* d_in, const int* in_sizes, int n_in,
                              void* d_out, int out_size)
{
    const float* obj    = (const float*)d_in[0];
    const float* pred   = (const float*)d_in[1];
    const int*   edges  = (const int*)d_in[2];
    const float* n1_w1  = (const float*)d_in[3];
    const float* n1_b1  = (const float*)d_in[4];
    const float* n1_w2  = (const float*)d_in[5];
    const float* n1_b2  = (const float*)d_in[6];
    const float* n2_w1  = (const float*)d_in[7];
    const float* n2_b1  = (const float*)d_in[8];
    const float* n2_w2  = (const float*)d_in[9];
    const float* n2_b2  = (const float*)d_in[10];
    const float* proj_w = (const float*)d_in[11];
    const float* proj_b = (const float*)d_in[12];
    const float* sim_w  = (const float*)d_in[13];
    const float* sim_b  = (const float*)d_in[14];

    float* out        = (float*)d_out;
    float* out_newobj = out;
    float* out_newp   = out + (size_t)NOBJ * DOUT_;

    float *cand, *z, *bu, *c0;
    int *cnt, *off, *cur, *eidx;
    __nv_bfloat16 *objs, *preds, *h1s, *prevs, *us, *h2s, *pooleds, *simws, *Ss;
    __nv_bfloat16 *wproj, *wn1a, *wn1b, *wn2a, *wn2b;
    cudaGetSymbolAddress((void**)&cand, g_cand);
    cudaGetSymbolAddress((void**)&z, g_z);
    cudaGetSymbolAddress((void**)&bu, g_bu);
    cudaGetSymbolAddress((void**)&c0, g_c0);
    cudaGetSymbolAddress((void**)&cnt, g_cnt);
    cudaGetSymbolAddress((void**)&off, g_off);
    cudaGetSymbolAddress((void**)&cur, g_cur);
    cudaGetSymbolAddress((void**)&eidx, g_eidx);
    cudaGetSymbolAddress((void**)&objs, g_objs);
    cudaGetSymbolAddress((void**)&preds, g_preds);
    cudaGetSymbolAddress((void**)&h1s, g_h1s);
    cudaGetSymbolAddress((void**)&prevs, g_prevs);
    cudaGetSymbolAddress((void**)&us, g_us);
    cudaGetSymbolAddress((void**)&h2s, g_h2s);
    cudaGetSymbolAddress((void**)&pooleds, g_pooleds);
    cudaGetSymbolAddress((void**)&simws, g_simws);
    cudaGetSymbolAddress((void**)&Ss, g_Ss);
    cudaGetSymbolAddress((void**)&wproj, g_wproj);
    cudaGetSymbolAddress((void**)&wn1a, g_wn1a);
    cudaGetSymbolAddress((void**)&wn1b, g_wn1b);
    cudaGetSymbolAddress((void**)&wn2a, g_wn2a);
    cudaGetSymbolAddress((void**)&wn2b, g_wn2b);

    cudaFuncSetAttribute(mmak<0,1,false,true>,  cudaFuncAttributeMaxDynamicSharedMemorySize, SMEMB);
    cudaFuncSetAttribute(mmak<0,1,false,false>, cudaFuncAttributeMaxDynamicSharedMemorySize, SMEMB);
    cudaFuncSetAttribute(mmak<1,1,true,true>,   cudaFuncAttributeMaxDynamicSharedMemorySize, SMEMB);
    cudaFuncSetAttribute(mmak<0,2,true,true>,   cudaFuncAttributeMaxDynamicSharedMemorySize, SMEMB);
    cudaFuncSetAttribute(mmak<0,1,true,true>,   cudaFuncAttributeMaxDynamicSharedMemorySize, SMEMB);
    cudaFuncSetAttribute(mmak<0,0,true,true>,   cudaFuncAttributeMaxDynamicSharedMemorySize, SMEMB);

    const int gO = (NOBJ + 63) / 64;    // 782
    const int gT = (NTRI + 63) / 64;    // 1563
    const dim3 blk(256);
    cudaStream_t s2 = g_sr.s2;

    // fork for s2
    cudaEventRecord(g_sr.evFork, 0);
    cudaStreamWaitEvent(s2, g_sr.evFork, 0);

    // s0: minimal critical path to n1a
    isplit2v<<<18750, 256>>>((const float4*)obj, (const float4*)pred, objs, preds);
    cudaEventRecord(g_sr.evInp, 0);
    wsplitA<<<768, 256>>>(n1_w1, wn1a);
    mmak<1,1,true,true><<<dim3(4, gT), blk, SMEMB>>>(nullptr, wn1a, n1_b1, nullptr, h1s,
        NTRI, 512, 384, objs, preds, edges, nullptr, nullptr);

    // s2: everything else (runs under n1a/n1b shadow)
    wsplitR<<<4864, 256, 0, s2>>>(n1_w2, proj_w, n2_w1, n2_w2, sim_w,
                                  wn1b, wproj, wn2a, wn2b, simws);
    cudaEventRecord(g_sr.evW2, s2);
    buk<<<65, 256, 0, s2>>>(sim_w, sim_b, bu, c0);
    zeroint<<<(NOBJ + 255) / 256, 256, 0, s2>>>(cnt, NOBJ);
    cntk<<<(2 * NTRI + 255) / 256, 256, 0, s2>>>(edges, cnt);
    scank<<<1, 1024, 0, s2>>>(cnt, off, cur);
    fillk<<<(2 * NTRI + 255) / 256, 256, 0, s2>>>(edges, cur, eidx);
    mmak<0,1,false,false><<<dim3(4, 8), blk, SMEMB, s2>>>(simws, simws, nullptr, nullptr, Ss,
        512, 512, 512, nullptr, nullptr, nullptr, nullptr, nullptr);
    cudaStreamWaitEvent(s2, g_sr.evInp, 0);
    mmak<0,1,false,true><<<dim3(4, gO), blk, SMEMB, s2>>>(objs, wproj, proj_b, nullptr, prevs,
        NOBJ, 512, 128, nullptr, nullptr, nullptr, nullptr, nullptr);
    zk3<<<(NOBJ * 32 + 255) / 256, 256, 0, s2>>>(prevs, bu, c0, z);
    mmak<0,1,false,true><<<dim3(4, gO), blk, SMEMB, s2>>>(prevs, Ss, bu, nullptr, us,
        NOBJ, 512, 512, nullptr, nullptr, nullptr, nullptr, nullptr);
    cudaEventRecord(g_sr.evJoin, s2);

    // s0: n1b (needs wn1b from s2)
    cudaStreamWaitEvent(0, g_sr.evW2, 0);
    mmak<0,2,true,true><<<dim3(9, gT), blk, SMEMB>>>(h1s, wn1b, n1_b2, nullptr, nullptr,
        NTRI, 1152, 512, nullptr, nullptr, nullptr, out_newp, cand);

    // join, then fused pooling + output MLP
    cudaStreamWaitEvent(0, g_sr.evJoin, 0);
    poolfk<<<(NOBJ * 32 + 255) / 256, 256>>>(off, eidx, us, z, cand, pooleds);
    mmak<0,1,true,true><<<dim3(4, gO), blk, SMEMB>>>(pooleds, wn2a, n2_b1, nullptr, h2s,
        NOBJ, 512, 512, nullptr, nullptr, nullptr, nullptr, nullptr);
    mmak<0,0,true,true><<<dim3(1, gO), blk, SMEMB>>>(h2s, wn2b, n2_b2, out_newobj, nullptr,
        NOBJ, 128, 512, nullptr, nullptr, nullptr, nullptr, nullptr);
}

// round 17
// speedup vs baseline: 1.0544x; 1.0544x over previous
#include <cuda_runtime.h>
#include <cuda_bf16.h>
#include <math.h>
#include <stdint.h>

#define NOBJ 50000
#define NTRI 100000
#define DIN_ 128
#define H_   512
#define DOUT_ 128

// ---------------- scratch (device globals: no allocs allowed) ----------------
static __device__ float    g_cand[(size_t)2 * NTRI * H_];   // fp32 (pool)
static __device__ float    g_z[NOBJ];
static __device__ float    g_bu[H_];
static __device__ float    g_c0[1];
static __device__ int      g_cnt[NOBJ];
static __device__ int      g_off[NOBJ + 1];
static __device__ int      g_cur[NOBJ];
static __device__ int      g_eidx[2 * NTRI];

// 2-term bf16 split planes [2][M][K]
static __device__ __nv_bfloat16 g_objs [(size_t)2 * NOBJ * DIN_];
static __device__ __nv_bfloat16 g_preds[(size_t)2 * NTRI * DIN_];
static __device__ __nv_bfloat16 g_h1s  [(size_t)2 * NTRI * H_];
static __device__ __nv_bfloat16 g_prevs[(size_t)2 * NOBJ * H_];
static __device__ __nv_bfloat16 g_us   [(size_t)2 * NOBJ * H_];
static __device__ __nv_bfloat16 g_h2s  [(size_t)2 * NOBJ * H_];
static __device__ __nv_bfloat16 g_pooleds[(size_t)2 * NOBJ * H_];
static __device__ __nv_bfloat16 g_simws[2 * 512 * 512];
static __device__ __nv_bfloat16 g_Ss   [2 * 512 * 512];

// 2-term bf16 split weights, [2][N][K]
static __device__ __nv_bfloat16 g_wproj[2 * 512 * 128];
static __device__ __nv_bfloat16 g_wn1a[2 * 512 * 384];
static __device__ __nv_bfloat16 g_wn1b[2 * 1152 * 512];
static __device__ __nv_bfloat16 g_wn2a[2 * 512 * 512];
static __device__ __nv_bfloat16 g_wn2b[2 * 128 * 512];

// ---------------- fork/join stream resources (host objects, created at load) ----------------
struct StreamRes {
    cudaStream_t s2;
    cudaEvent_t evFork, evInp, evW2, evJoin, evCand, evC;
    StreamRes() {
        cudaStreamCreateWithFlags(&s2, cudaStreamNonBlocking);
        cudaEventCreateWithFlags(&evFork, cudaEventDisableTiming);
        cudaEventCreateWithFlags(&evInp,  cudaEventDisableTiming);
        cudaEventCreateWithFlags(&evW2,   cudaEventDisableTiming);
        cudaEventCreateWithFlags(&evJoin, cudaEventDisableTiming);
        cudaEventCreateWithFlags(&evCand, cudaEventDisableTiming);
        cudaEventCreateWithFlags(&evC,    cudaEventDisableTiming);
    }
};
static StreamRes g_sr;

// ---------------- helpers ----------------
__device__ __forceinline__ void split2(float x, unsigned short& hi, unsigned short& lo) {
    __nv_bfloat16 h = __float2bfloat16_rn(x);
    __nv_bfloat16 l = __float2bfloat16_rn(x - __bfloat162float(h));
    hi = __bfloat16_as_ushort(h);
    lo = __bfloat16_as_ushort(l);
}
__device__ __forceinline__ float2 bf2(uint32_t u) {
    return make_float2(__bfloat162float(__ushort_as_bfloat16((unsigned short)(u & 0xffff))),
                       __bfloat162float(__ushort_as_bfloat16((unsigned short)(u >> 16))));
}
__device__ __forceinline__ uint32_t smem_u32(const void* p) {
    uint32_t a;
    asm("{ .reg .u64 t; cvta.to.shared.u64 t, %1; cvt.u32.u64 %0, t; }" : "=r"(a) : "l"(p));
    return a;
}
__device__ __forceinline__ void cpa16(uint32_t dst, const void* src, uint32_t sz) {
    asm volatile("cp.async.cg.shared.global [%0], [%1], 16, %2;"
                 :: "r"(dst), "l"(src), "r"(sz) : "memory");
}
#define CPA_COMMIT() asm volatile("cp.async.commit_group;" ::: "memory")
#define CPA_WAIT0()  asm volatile("cp.async.wait_group 0;" ::: "memory")

__device__ __forceinline__ void mma16816(float* d, const uint32_t* a, uint32_t b0, uint32_t b1) {
    asm volatile(
        "mma.sync.aligned.m16n8k16.row.col.f32.bf16.bf16.f32 "
        "{%0,%1,%2,%3}, {%4,%5,%6,%7}, {%8,%9}, {%0,%1,%2,%3};"
        : "+f"(d[0]), "+f"(d[1]), "+f"(d[2]), "+f"(d[3])
        : "r"(a[0]), "r"(a[1]), "r"(a[2]), "r"(a[3]), "r"(b0), "r"(b1));
}
__device__ __forceinline__ void ldsm4(uint32_t* r, uint32_t addr) {
    asm volatile("ldmatrix.sync.aligned.m8n8.x4.shared.b16 {%0,%1,%2,%3}, [%4];"
                 : "=r"(r[0]), "=r"(r[1]), "=r"(r[2]), "=r"(r[3]) : "r"(addr));
}

// ---------------- prologue split kernels ----------------
__global__ void wsplitA(const float* __restrict__ n1w1, __nv_bfloat16* __restrict__ wn1a)
{
    const int idx = blockIdx.x * 256 + threadIdx.x;
    const size_t NK = (size_t)512 * 384;
    if (idx >= (int)NK) return;
    const int n = idx / 384, k = idx - n * 384;
    unsigned short a, bb;
    split2(n1w1[(size_t)k * 512 + n], a, bb);
    wn1a[idx]      = __ushort_as_bfloat16(a);
    wn1a[NK + idx] = __ushort_as_bfloat16(bb);
}

// [0,2304) wn1b | [2304,2560) wproj | [2560,3584) wn2a | [3584,3840) wn2b | [3840,4864) simws
__global__ void wsplitR(const float* __restrict__ n1w2, const float* __restrict__ projw,
                        const float* __restrict__ n2w1, const float* __restrict__ n2w2,
                        const float* __restrict__ simw,
                        __nv_bfloat16* __restrict__ wn1b, __nv_bfloat16* __restrict__ wproj,
                        __nv_bfloat16* __restrict__ wn2a, __nv_bfloat16* __restrict__ wn2b,
                        __nv_bfloat16* __restrict__ simws)
{
    const int b = blockIdx.x;
    const float* W; __nv_bfloat16* out; int Kd, Nd, base; bool trans = true;
    if (b < 2304)      { W = n1w2;  out = wn1b;  Kd = 512; Nd = 1152; base = 0; }
    else if (b < 2560) { W = projw; out = wproj; Kd = 128; Nd = 512;  base = 2304; }
    else if (b < 3584) { W = n2w1;  out = wn2a;  Kd = 512; Nd = 512;  base = 2560; }
    else if (b < 3840) { W = n2w2;  out = wn2b;  Kd = 512; Nd = 128;  base = 3584; }
    else               { W = simw;  out = simws; Kd = 512; Nd = 512;  base = 3840; trans = false; }
    const int idx = (b - base) * 256 + threadIdx.x;
    const size_t NK = (size_t)Nd * Kd;
    if (idx >= (int)NK) return;
    float v;
    if (trans) { const int n = idx / Kd, k = idx - n * Kd; v = W[(size_t)k * Nd + n]; }
    else       v = W[idx];
    unsigned short a, bb;
    split2(v, a, bb);
    out[idx]      = __ushort_as_bfloat16(a);
    out[NK + idx] = __ushort_as_bfloat16(bb);
}

// vectorized input split: one thread = 4 consecutive floats
__global__ void isplit2v(const float4* __restrict__ obj, const float4* __restrict__ pred,
                         __nv_bfloat16* __restrict__ objs, __nv_bfloat16* __restrict__ preds)
{
    const int b = blockIdx.x;
    const float4* src; __nv_bfloat16* dst; int n4, idx;
    if (b < 6250) { src = obj;  dst = objs;  n4 = NOBJ * DIN_ / 4; idx = b * 256 + threadIdx.x; }
    else          { src = pred; dst = preds; n4 = NTRI * DIN_ / 4; idx = (b - 6250) * 256 + threadIdx.x; }
    if (idx >= n4) return;
    const float4 v = src[idx];
    unsigned short h0, l0, h1, l1, h2, l2, h3, l3;
    split2(v.x, h0, l0); split2(v.y, h1, l1);
    split2(v.z, h2, l2); split2(v.w, h3, l3);
    *(uint2*)(dst + idx * 4) =
        make_uint2((uint32_t)h0 | ((uint32_t)h1 << 16), (uint32_t)h2 | ((uint32_t)h3 << 16));
    *(uint2*)(dst + (size_t)n4 * 4 + idx * 4) =
        make_uint2((uint32_t)l0 | ((uint32_t)l1 << 16), (uint32_t)l2 | ((uint32_t)l3 << 16));
}

__global__ void buk(const float* __restrict__ simw, const float* __restrict__ simb,
                    float* __restrict__ bu, float* __restrict__ c0)
{
    const int warp = (blockIdx.x * blockDim.x + threadIdx.x) >> 5;
    const int lane = threadIdx.x & 31;
    if (warp > H_) return;
    const float4* a = (warp < H_) ? (const float4*)(simw + (size_t)warp * H_)
                                  : (const float4*)simb;
    const float4* b = (const float4*)simb;
    float s = 0.f;
    #pragma unroll
    for (int q = 0; q < 4; q++) {
        float4 x = a[lane + q * 32], y = b[lane + q * 32];
        s += x.x * y.x + x.y * y.y + x.z * y.z + x.w * y.w;
    }
    #pragma unroll
    for (int o = 16; o; o >>= 1) s += __shfl_down_sync(0xffffffffu, s, o);
    if (lane == 0) {
        if (warp < H_) bu[warp] = s;
        else           c0[0] = s;
    }
}

// ---------------- HMMA GEMM: D[M,N] = A[M,K] @ Ws^T (128x128 tile, 2 CTA/SM) ----------------
#define APITCH 80
#define PLANE  (128 * APITCH)
#define SMEMB  (8 * PLANE)

template<int AMODE, int OMODE, bool RELU, bool HASBIAS>
__global__ __launch_bounds__(256, 2)
void mmak(const __nv_bfloat16* __restrict__ As,
          const __nv_bfloat16* __restrict__ Wt,
          const float* __restrict__ bias, float* __restrict__ Cf,
          __nv_bfloat16* __restrict__ Cs,
          int M, int N, int K, int nbase,
          const __nv_bfloat16* __restrict__ objs, const __nv_bfloat16* __restrict__ preds,
          const int* __restrict__ edges,
          float* __restrict__ outp, float* __restrict__ candp)
{
    extern __shared__ __align__(16) unsigned char sm[];
    const int tid = threadIdx.x;
    const int lane = tid & 31, wid = tid >> 5;
    const int wr = wid >> 2, wc = wid & 3;
    const int bm = blockIdx.y * 128, bn = blockIdx.x * 128 + nbase;
    const size_t MK = (size_t)M * K, NK = (size_t)N * K, MN = (size_t)M * N;
    const uint32_t sb = smem_u32(sm);
    const int arow = lane >> 2, acol = (lane & 3) << 1;
    const int t8 = lane & 7, quad = lane >> 3;

    const uint32_t aoff = (uint32_t)(wr * 64 + t8 + ((quad & 1) << 3)) * APITCH + ((quad >> 1) << 4);
    const uint32_t boff = 2 * PLANE +
        (uint32_t)(wc * 32 + t8 + ((quad >> 1) << 3)) * APITCH + ((quad & 1) << 4);

    float acc[4][4][4];
    #pragma unroll
    for (int i = 0; i < 4; i++)
        #pragma unroll
        for (int j = 0; j < 4; j++)
            #pragma unroll
            for (int q = 0; q < 4; q++) acc[i][j][q] = 0.f;

    auto stageAsync = [&](int k0, int b) {
        const uint32_t smA = sb + b * 4 * PLANE;
        const uint32_t smB = smA + 2 * PLANE;
        if (AMODE == 0) {
            #pragma unroll
            for (int it = 0; it < 4; it++) {
                const int idx = (it << 8) + tid;
                const int p = idx >> 9, r = (idx >> 2) & 127, seg = idx & 3;
                const int gm = bm + r;
                const int gmc = gm < M ? gm : M - 1;
                const __nv_bfloat16* src = As + (size_t)p * MK + (size_t)gmc * K + k0 + seg * 8;
                cpa16(smA + p * PLANE + r * APITCH + seg * 16, src, gm < M ? 16u : 0u);
            }
        } else {
            #pragma unroll
            for (int it = 0; it < 4; it++) {
                const int idx = (it << 8) + tid;
                const int p = idx >> 9, r = (idx >> 2) & 127, seg = idx & 3;
                const int gm = bm + r;
                const int gmc = gm < M ? gm : M - 1;
                const __nv_bfloat16* src;
                if (k0 < DIN_)
                    src = objs + (size_t)p * ((size_t)NOBJ * DIN_)
                        + (size_t)edges[2 * gmc] * DIN_ + k0 + seg * 8;
                else if (k0 < 2 * DIN_)
                    src = preds + (size_t)p * ((size_t)NTRI * DIN_)
                        + (size_t)gmc * DIN_ + (k0 - DIN_) + seg * 8;
                else
                    src = objs + (size_t)p * ((size_t)NOBJ * DIN_)
                        + (size_t)edges[2 * gmc + 1] * DIN_ + (k0 - 2 * DIN_) + seg * 8;
                cpa16(smA + p * PLANE + r * APITCH + seg * 16, src, gm < M ? 16u : 0u);
            }
        }
        #pragma unroll
        for (int it = 0; it < 4; it++) {
            const int idx = (it << 8) + tid;
            const int p = idx >> 9, n = (idx >> 2) & 127, seg = idx & 3;
            const __nv_bfloat16* src = Wt + (size_t)p * NK + (size_t)(bn + n) * K + k0 + seg * 8;
            cpa16(smB + p * PLANE + n * APITCH + seg * 16, src, 16u);
        }
        CPA_COMMIT();
    };

    auto compute = [&](int b) {
        const uint32_t buf = sb + b * 4 * PLANE;
        #pragma unroll
        for (int s = 0; s < 2; s++) {
            const uint32_t ksb = s * 32;
            uint32_t afh[4][4], afl[4][4], bh[4][2], bl[4][2];
            #pragma unroll
            for (int i = 0; i < 4; i++)
                ldsm4(afh[i], buf + aoff + i * 16 * APITCH + ksb);
            #pragma unroll
            for (int jj = 0; jj < 2; jj++)
                ldsm4(&bh[jj * 2][0], buf + boff + jj * 16 * APITCH + ksb);
            #pragma unroll
            for (int i = 0; i < 4; i++)
                ldsm4(afl[i], buf + PLANE + aoff + i * 16 * APITCH + ksb);
            #pragma unroll
            for (int j = 0; j < 4; j++)
                #pragma unroll
                for (int i = 0; i < 4; i++)
                    mma16816(acc[i][j], afh[i], bh[j][0], bh[j][1]);
            #pragma unroll
            for (int jj = 0; jj < 2; jj++)
                ldsm4(&bl[jj * 2][0], buf + PLANE + boff + jj * 16 * APITCH + ksb);
            #pragma unroll
            for (int j = 0; j < 4; j++)
                #pragma unroll
                for (int i = 0; i < 4; i++)
                    mma16816(acc[i][j], afl[i], bh[j][0], bh[j][1]);
            #pragma unroll
            for (int j = 0; j < 4; j++)
                #pragma unroll
                for (int i = 0; i < 4; i++)
                    mma16816(acc[i][j], afh[i], bl[j][0], bl[j][1]);
        }
    };

    const int nch = K >> 5;
    stageAsync(0, 0);
    CPA_WAIT0();
    __syncthreads();

    for (int ch = 0; ch < nch; ch++) {
        const int b = ch & 1;
        if (ch + 1 < nch) stageAsync((ch + 1) << 5, b ^ 1);
        compute(b);
        CPA_WAIT0();
        __syncthreads();
    }

    // ---- epilogue ----
    #pragma unroll
    for (int i = 0; i < 4; i++)
        #pragma unroll
        for (int j = 0; j < 4; j++) {
            const int gm0 = bm + wr * 64 + i * 16 + arow;
            const int gn  = bn + wc * 32 + j * 8 + acol;
            float2 bb = make_float2(0.f, 0.f);
            if (HASBIAS) bb = *(const float2*)&bias[gn];
            #pragma unroll
            for (int h = 0; h < 2; h++) {
                const int m = gm0 + h * 8;
                if (m < M) {
                    float x0 = acc[i][j][2 * h]     + bb.x;
                    float x1 = acc[i][j][2 * h + 1] + bb.y;
                    if (RELU) { x0 = fmaxf(x0, 0.f); x1 = fmaxf(x1, 0.f); }
                    if (OMODE == 0) {
                        *(float2*)(Cf + (size_t)m * N + gn) = make_float2(x0, x1);
                    } else if (OMODE == 1) {
                        unsigned short h0, l0, h1, l1;
                        split2(x0, h0, l0); split2(x1, h1, l1);
                        *(uint32_t*)(Cs + (size_t)m * N + gn)      = (uint32_t)h0 | ((uint32_t)h1 << 16);
                        *(uint32_t*)(Cs + MN + (size_t)m * N + gn) = (uint32_t)l0 | ((uint32_t)l1 << 16);
                    } else {
                        float* dst;
                        if (gn < H_)              dst = candp + (size_t)m * H_ + gn;
                        else if (gn < H_ + DOUT_) dst = outp + (size_t)m * DOUT_ + (gn - H_);
                        else                      dst = candp + (size_t)(NTRI + m) * H_ + (gn - H_ - DOUT_);
                        *(float2*)dst = make_float2(x0, x1);
                    }
                }
            }
        }
}

// ---------------- z + CSR build + fused online-softmax pooling ----------------
__global__ void zk3(const __nv_bfloat16* __restrict__ prevs, const float* __restrict__ bu,
                    const float* __restrict__ c0, float* __restrict__ z)
{
    const int row = (blockIdx.x * blockDim.x + threadIdx.x) >> 5;
    const int lane = threadIdx.x & 31;
    if (row >= NOBJ) return;
    const size_t PS = (size_t)NOBJ * H_;
    const uint2* ph = (const uint2*)(prevs + (size_t)row * H_);
    const uint2* pl = (const uint2*)(prevs + PS + (size_t)row * H_);
    float s = 0.f;
    #pragma unroll
    for (int q = 0; q < 4; q++) {
        const int t = lane + q * 32;
        uint2 a = ph[t], b = pl[t];
        float4 w4 = *(const float4*)&bu[t * 4];
        float2 a0 = bf2(a.x), a1 = bf2(a.y), b0 = bf2(b.x), b1 = bf2(b.y);
        s += (a0.x + b0.x) * w4.x + (a0.y + b0.y) * w4.y
           + (a1.x + b1.x) * w4.z + (a1.y + b1.y) * w4.w;
    }
    #pragma unroll
    for (int o = 16; o; o >>= 1) s += __shfl_down_sync(0xffffffffu, s, o);
    if (lane == 0) z[row] = s + c0[0];
}

__global__ void zeroint(int* __restrict__ p, int n)
{
    const int i = blockIdx.x * blockDim.x + threadIdx.x;
    if (i < n) p[i] = 0;
}

__global__ void cntk(const int* __restrict__ edges, int* __restrict__ cnt)
{
    const int e = blockIdx.x * blockDim.x + threadIdx.x;
    if (e >= 2 * NTRI) return;
    const int idx = (e < NTRI) ? edges[2 * e] : edges[2 * (e - NTRI) + 1];
    atomicAdd(cnt + idx, 1);
}

__global__ void scank(const int* __restrict__ cnt, int* __restrict__ off,
                      int* __restrict__ cur)
{
    __shared__ int ssum[1024];
    const int t = threadIdx.x;
    const int CH = (NOBJ + 1023) / 1024;
    const int base = t * CH;
    int s = 0;
    for (int i = 0; i < CH; i++) {
        const int j = base + i;
        if (j < NOBJ) s += cnt[j];
    }
    ssum[t] = s;
    __syncthreads();
    for (int d = 1; d < 1024; d <<= 1) {
        const int v = (t >= d) ? ssum[t - d] : 0;
        __syncthreads();
        ssum[t] += v;
        __syncthreads();
    }
    int run = t ? ssum[t - 1] : 0;
    for (int i = 0; i < CH; i++) {
        const int j = base + i;
        if (j < NOBJ) {
            off[j] = run;
            cur[j] = run;
            run += cnt[j];
        }
    }
    if (t == 1023) off[NOBJ] = ssum[1023];
}

__global__ void fillk(const int* __restrict__ edges, int* __restrict__ cur,
                      int* __restrict__ eidx)
{
    const int e = blockIdx.x * blockDim.x + threadIdx.x;
    if (e >= 2 * NTRI) return;
    const int idx = (e < NTRI) ? edges[2 * e] : edges[2 * (e - NTRI) + 1];
    const int pos = atomicAdd(cur + idx, 1);
    eidx[pos] = e;
}

// warp per object: one pass, online softmax (exact)
__global__ void poolfk(const int* __restrict__ off, const int* __restrict__ eidx,
                       const __nv_bfloat16* __restrict__ us, const float* __restrict__ z,
                       const float* __restrict__ cand, __nv_bfloat16* __restrict__ pooleds)
{
    const int i = (blockIdx.x * blockDim.x + threadIdx.x) >> 5;
    const int lane = threadIdx.x & 31;
    if (i >= NOBJ) return;
    const size_t PS = (size_t)NOBJ * H_;

    float4 uf[4];
    {
        const uint2* uh = (const uint2*)(us + (size_t)i * H_);
        const uint2* ul = (const uint2*)(us + PS + (size_t)i * H_);
        #pragma unroll
        for (int q = 0; q < 4; q++) {
            uint2 h = uh[lane + q * 32], l = ul[lane + q * 32];
            float2 h0 = bf2(h.x), h1 = bf2(h.y), l0 = bf2(l.x), l1 = bf2(l.y);
            uf[q] = make_float4(h0.x + l0.x, h0.y + l0.y, h1.x + l1.x, h1.y + l1.y);
        }
    }
    const float zi = z[i];
    float m = zi, den = 1.f;
    float4 a0 = make_float4(0, 0, 0, 0), a1 = a0, a2 = a0, a3 = a0;

    const int beg = off[i], end = off[i + 1];
    for (int p = beg; p < end; p++) {
        const int e = eidx[p];
        const float4* src = (const float4*)(cand + (size_t)e * H_);
        float4 c0v = src[lane], c1v = src[lane + 32], c2v = src[lane + 64], c3v = src[lane + 96];
        float s = c0v.x * uf[0].x + c0v.y * uf[0].y + c0v.z * uf[0].z + c0v.w * uf[0].w
                + c1v.x * uf[1].x + c1v.y * uf[1].y + c1v.z * uf[1].z + c1v.w * uf[1].w
                + c2v.x * uf[2].x + c2v.y * uf[2].y + c2v.z * uf[2].z + c2v.w * uf[2].w
                + c3v.x * uf[3].x + c3v.y * uf[3].y + c3v.z * uf[3].z + c3v.w * uf[3].w;
        #pragma unroll
        for (int o = 16; o; o >>= 1) s += __shfl_xor_sync(0xffffffffu, s, o);
        const float score = s + zi;
        float w;
        if (score > m) {
            const float sc = expf(m - score);
            den *= sc;
            a0.x *= sc; a0.y *= sc; a0.z *= sc; a0.w *= sc;
            a1.x *= sc; a1.y *= sc; a1.z *= sc; a1.w *= sc;
            a2.x *= sc; a2.y *= sc; a2.z *= sc; a2.w *= sc;
            a3.x *= sc; a3.y *= sc; a3.z *= sc; a3.w *= sc;
            m = score;
            w = 1.f;
        } else {
            w = expf(score - m);
        }
        den += w;
        a0.x += w * c0v.x; a0.y += w * c0v.y; a0.z += w * c0v.z; a0.w += w * c0v.w;
        a1.x += w * c1v.x; a1.y += w * c1v.y; a1.z += w * c1v.z; a1.w += w * c1v.w;
        a2.x += w * c2v.x; a2.y += w * c2v.y; a2.z += w * c2v.z; a2.w += w * c2v.w;
        a3.x += w * c3v.x; a3.y += w * c3v.y; a3.z += w * c3v.z; a3.w += w * c3v.w;
    }

    const float r = 1.0f / den;
    __nv_bfloat16* hi = pooleds + (size_t)i * H_;
    __nv_bfloat16* lo = pooleds + PS + (size_t)i * H_;
    auto st = [&](float4 v, int col) {
        v.x *= r; v.y *= r; v.z *= r; v.w *= r;
        unsigned short h0, l0, h1, l1, h2, l2, h3, l3;
        split2(v.x, h0, l0); split2(v.y, h1, l1);
        split2(v.z, h2, l2); split2(v.w, h3, l3);
        *(uint2*)(hi + col) = make_uint2((uint32_t)h0 | ((uint32_t)h1 << 16),
                                         (uint32_t)h2 | ((uint32_t)h3 << 16));
        *(uint2*)(lo + col) = make_uint2((uint32_t)l0 | ((uint32_t)l1 << 16),
                                         (uint32_t)l2 | ((uint32_t)l3 << 16));
    };
    st(a0, 4 * lane);
    st(a1, 128 + 4 * lane);
    st(a2, 256 + 4 * lane);
    st(a3, 384 + 4 * lane);
}

extern "C" void kernel_launch(void* const* d_in, const int* in_sizes, int n_in,
                              void* d_out, int out_size)
{
    const float* obj    = (const float*)d_in[0];
    const float* pred   = (const float*)d_in[1];
    const int*   edges  = (const int*)d_in[2];
    const float* n1_w1  = (const float*)d_in[3];
    const float* n1_b1  = (const float*)d_in[4];
    const float* n1_w2  = (const float*)d_in[5];
    const float* n1_b2  = (const float*)d_in[6];
    const float* n2_w1  = (const float*)d_in[7];
    const float* n2_b1  = (const float*)d_in[8];
    const float* n2_w2  = (const float*)d_in[9];
    const float* n2_b2  = (const float*)d_in[10];
    const float* proj_w = (const float*)d_in[11];
    const float* proj_b = (const float*)d_in[12];
    const float* sim_w  = (const float*)d_in[13];
    const float* sim_b  = (const float*)d_in[14];

    float* out        = (float*)d_out;
    float* out_newobj = out;
    float* out_newp   = out + (size_t)NOBJ * DOUT_;

    float *cand, *z, *bu, *c0;
    int *cnt, *off, *cur, *eidx;
    __nv_bfloat16 *objs, *preds, *h1s, *prevs, *us, *h2s, *pooleds, *simws, *Ss;
    __nv_bfloat16 *wproj, *wn1a, *wn1b, *wn2a, *wn2b;
    cudaGetSymbolAddress((void**)&cand, g_cand);
    cudaGetSymbolAddress((void**)&z, g_z);
    cudaGetSymbolAddress((void**)&bu, g_bu);
    cudaGetSymbolAddress((void**)&c0, g_c0);
    cudaGetSymbolAddress((void**)&cnt, g_cnt);
    cudaGetSymbolAddress((void**)&off, g_off);
    cudaGetSymbolAddress((void**)&cur, g_cur);
    cudaGetSymbolAddress((void**)&eidx, g_eidx);
    cudaGetSymbolAddress((void**)&objs, g_objs);
    cudaGetSymbolAddress((void**)&preds, g_preds);
    cudaGetSymbolAddress((void**)&h1s, g_h1s);
    cudaGetSymbolAddress((void**)&prevs, g_prevs);
    cudaGetSymbolAddress((void**)&us, g_us);
    cudaGetSymbolAddress((void**)&h2s, g_h2s);
    cudaGetSymbolAddress((void**)&pooleds, g_pooleds);
    cudaGetSymbolAddress((void**)&simws, g_simws);
    cudaGetSymbolAddress((void**)&Ss, g_Ss);
    cudaGetSymbolAddress((void**)&wproj, g_wproj);
    cudaGetSymbolAddress((void**)&wn1a, g_wn1a);
    cudaGetSymbolAddress((void**)&wn1b, g_wn1b);
    cudaGetSymbolAddress((void**)&wn2a, g_wn2a);
    cudaGetSymbolAddress((void**)&wn2b, g_wn2b);

    cudaFuncSetAttribute(mmak<0,1,false,true>,  cudaFuncAttributeMaxDynamicSharedMemorySize, SMEMB);
    cudaFuncSetAttribute(mmak<0,1,false,false>, cudaFuncAttributeMaxDynamicSharedMemorySize, SMEMB);
    cudaFuncSetAttribute(mmak<1,1,true,true>,   cudaFuncAttributeMaxDynamicSharedMemorySize, SMEMB);
    cudaFuncSetAttribute(mmak<0,2,true,true>,   cudaFuncAttributeMaxDynamicSharedMemorySize, SMEMB);
    cudaFuncSetAttribute(mmak<0,1,true,true>,   cudaFuncAttributeMaxDynamicSharedMemorySize, SMEMB);
    cudaFuncSetAttribute(mmak<0,0,true,true>,   cudaFuncAttributeMaxDynamicSharedMemorySize, SMEMB);

    const int gO = (NOBJ + 127) / 128;   // 391
    const int gT = (NTRI + 127) / 128;   // 782
    const dim3 blk(256);
    cudaStream_t s2 = g_sr.s2;

    // fork for s2
    cudaEventRecord(g_sr.evFork, 0);
    cudaStreamWaitEvent(s2, g_sr.evFork, 0);

    // s0: minimal critical path to n1a (vectorized input split)
    isplit2v<<<18750, 256>>>((const float4*)obj, (const float4*)pred, objs, preds);
    cudaEventRecord(g_sr.evInp, 0);
    wsplitA<<<768, 256>>>(n1_w1, wn1a);
    mmak<1,1,true,true><<<dim3(4, gT), blk, SMEMB>>>(nullptr, wn1a, n1_b1, nullptr, h1s,
        NTRI, 512, 384, 0, objs, preds, edges, nullptr, nullptr);

    // s2: everything else (runs under n1a/n1b shadow)
    wsplitR<<<4864, 256, 0, s2>>>(n1_w2, proj_w, n2_w1, n2_w2, sim_w,
                                  wn1b, wproj, wn2a, wn2b, simws);
    cudaEventRecord(g_sr.evW2, s2);
    buk<<<65, 256, 0, s2>>>(sim_w, sim_b, bu, c0);
    zeroint<<<(NOBJ + 255) / 256, 256, 0, s2>>>(cnt, NOBJ);
    cntk<<<(2 * NTRI + 255) / 256, 256, 0, s2>>>(edges, cnt);
    scank<<<1, 1024, 0, s2>>>(cnt, off, cur);
    fillk<<<(2 * NTRI + 255) / 256, 256, 0, s2>>>(edges, cur, eidx);
    mmak<0,1,false,false><<<dim3(4, 4), blk, SMEMB, s2>>>(simws, simws, nullptr, nullptr, Ss,
        512, 512, 512, 0, nullptr, nullptr, nullptr, nullptr, nullptr);
    cudaStreamWaitEvent(s2, g_sr.evInp, 0);
    mmak<0,1,false,true><<<dim3(4, gO), blk, SMEMB, s2>>>(objs, wproj, proj_b, nullptr, prevs,
        NOBJ, 512, 128, 0, nullptr, nullptr, nullptr, nullptr, nullptr);
    zk3<<<(NOBJ * 32 + 255) / 256, 256, 0, s2>>>(prevs, bu, c0, z);
    mmak<0,1,false,true><<<dim3(4, gO), blk, SMEMB, s2>>>(prevs, Ss, bu, nullptr, us,
        NOBJ, 512, 512, 0, nullptr, nullptr, nullptr, nullptr, nullptr);
    cudaEventRecord(g_sr.evJoin, s2);

    // s0: n1b cand-only column tiles (needs wn1b from s2)
    cudaStreamWaitEvent(0, g_sr.evW2, 0);
    mmak<0,2,true,true><<<dim3(4, gT), blk, SMEMB>>>(h1s, wn1b, n1_b2, nullptr, nullptr,
        NTRI, 1152, 512, 0, nullptr, nullptr, nullptr, out_newp, cand);      // n in [0,512)
    mmak<0,2,true,true><<<dim3(4, gT), blk, SMEMB>>>(h1s, wn1b, n1_b2, nullptr, nullptr,
        NTRI, 1152, 512, 640, nullptr, nullptr, nullptr, out_newp, cand);    // n in [640,1152)
    cudaEventRecord(g_sr.evCand, 0);

    // s2: new_p column tile, deferred to overlap the memory-bound pooling phase
    cudaStreamWaitEvent(s2, g_sr.evCand, 0);
    mmak<0,2,true,true><<<dim3(1, gT), blk, SMEMB, s2>>>(h1s, wn1b, n1_b2, nullptr, nullptr,
        NTRI, 1152, 512, 512, nullptr, nullptr, nullptr, out_newp, cand);    // n in [512,640)
    cudaEventRecord(g_sr.evC, s2);

    // s0 tail: fused pooling + output MLP (newp GEMM overlaps poolfk/n2a)
    cudaStreamWaitEvent(0, g_sr.evJoin, 0);
    poolfk<<<(NOBJ * 32 + 255) / 256, 256>>>(off, eidx, us, z, cand, pooleds);
    mmak<0,1,true,true><<<dim3(4, gO), blk, SMEMB>>>(pooleds, wn2a, n2_b1, nullptr, h2s,
        NOBJ, 512, 512, 0, nullptr, nullptr, nullptr, nullptr, nullptr);
    cudaStreamWaitEvent(0, g_sr.evC, 0);
    mmak<0,0,true,true><<<dim3(1, gO), blk, SMEMB>>>(h2s, wn2b, n2_b2, out_newobj, nullptr,
        NOBJ, 128, 512, 0, nullptr, nullptr, nullptr, nullptr, nullptr);
}